// round 14
// baseline (speedup 1.0000x reference)
#include <cuda_runtime.h>
#include <math.h>

#define NB   256            // graphs
#define NRr  268            // ROIs per graph
#define NT   (NB*NRr)       // total nodes = 68608
#define IC   256
#define OC   64
#define NCm  7
#define DEG  32
#define EPG  (NRr*DEG)      // edges per graph = 8576
#define ET   (NT*DEG)       // total edges = 2195456
#define KK   214            // top-k per graph
#define QT   256            // sigmoid table resolution
#define LN_EPS 1e-5f
#define CHUNK (EPG/8)       // 1072 edges per warp in k_csr

// k_xt smem layout
#define XS_STRIDE 68        // 256 rows (graphs) x 64 k, padded
#define WS_STRIDE 72        // 64 rows (k) x 64 out, halves at col 0 and 36
#define XS_FLOATS (256*XS_STRIDE)
#define WS_FLOATS (64*WS_STRIDE)

// output layout (float32, concatenated in reference return order)
#define XP_OFF   0
#define BAT_OFF  (NB*KK*OC)                 // 3506176
#define SC_OFF   (BAT_OFF + NB*KK)          // 3560960
#define PERM_OFF (SC_OFF + NT)              // 3629568

// ---------------- scratch (device globals; no allocation allowed) ----------
__device__ float g_tab2[QT*OC*2];           // per q,c: (sigmoid, delta) pairs, 128 KB
__device__ float g_selfg[OC];               // exact gate at ea=1 (self loops)
__device__ float g_xt[NT*OC];               // xt (per-node transform result)
__device__ float g_out[NT*OC];              // h after fused conv+ELU+LN
__device__ int   g_bsrc[ET];                // CSR bucket: global src node per slot
__device__ float g_bea[ET];                 // CSR bucket: edge_attr per slot
__device__ int   g_off[NT+1];               // CSR offsets (global edge space)

// ---------------- kernels --------------------------------------------------
__global__ void k_tab(const float* __restrict__ w, const float* __restrict__ b) {
    int q = blockIdx.x, c = threadIdx.x;    // grid QT+1
    double wa = (double)w[c], ba = (double)b[c];
    if (q == QT) {
        g_selfg[c] = (float)(1.0 / (1.0 + exp(-(wa + ba))));
        return;
    }
    double v0 = 1.0 / (1.0 + exp(-(((double)q    /(double)QT)*wa + ba)));
    double v1 = 1.0 / (1.0 + exp(-(((double)(q+1)/(double)QT)*wa + ba)));
    g_tab2[q*(OC*2) + c*2]     = (float)v0;
    g_tab2[q*(OC*2) + c*2 + 1] = (float)(v1 - v0);
}

// Fused ROI-kernel mix + grouped GEMM, smem-staged.
// Block = ROI r. Thread = 2 graphs x 32 outputs.
__global__ void __launch_bounds__(256, 2) k_xt(const float* __restrict__ x,
                                               const float* __restrict__ basis,
                                               const float* __restrict__ rc) {
    extern __shared__ float sm[];           // [XS_FLOATS] X | [WS_FLOATS] W
    float* Xs = sm;
    float* Ws = sm + XS_FLOATS;
    __shared__ float cws[NCm];
    int r = blockIdx.x;
    int tid = threadIdx.x;
    int w = tid >> 5, lane = tid & 31;
    int gp = tid >> 1;                      // 0..127
    int oh = tid & 1;                       // output half
    int g0 = gp, g1 = gp + 128;
    int woff = oh ? 36 : 0;

    if (tid == 0) {
        double v[NCm]; double m = -1e300;
        #pragma unroll
        for (int c = 0; c < NCm; c++) { v[c] = (double)rc[r*NCm + c]; if (v[c] > m) m = v[c]; }
        double s = 0.0;
        #pragma unroll
        for (int c = 0; c < NCm; c++) { v[c] = exp(v[c] - m); s += v[c]; }
        #pragma unroll
        for (int c = 0; c < NCm; c++) cws[c] = (float)(v[c] / s);
    }
    __syncthreads();
    float cwv[NCm];
    #pragma unroll
    for (int c = 0; c < NCm; c++) cwv[c] = cws[c];

    float4 a0[8], a1[8];
    #pragma unroll
    for (int j = 0; j < 8; j++) {
        a0[j] = make_float4(0.f,0.f,0.f,0.f);
        a1[j] = make_float4(0.f,0.f,0.f,0.f);
    }
    const float4* b4 = (const float4*)basis;

    for (int kt = 0; kt < 4; kt++) {
        __syncthreads();
        for (int i = tid; i < 64*16; i += 256) {
            int kk = i >> 4, c4 = i & 15;
            float4 acc = make_float4(0.f,0.f,0.f,0.f);
            #pragma unroll
            for (int c = 0; c < NCm; c++) {
                float4 t = b4[c*(IC*OC/4) + (kt*64 + kk)*(OC/4) + c4];
                acc.x += cwv[c]*t.x; acc.y += cwv[c]*t.y;
                acc.z += cwv[c]*t.z; acc.w += cwv[c]*t.w;
            }
            int col = c4*4;
            int off = (col < 32) ? col : (36 + col - 32);
            *(float4*)(Ws + kk*WS_STRIDE + off) = acc;
        }
        for (int g = w; g < 256; g += 8) {
            float2 v = ((const float2*)(x + ((size_t)(g*NRr + r))*IC + kt*64))[lane];
            ((float2*)(Xs + g*XS_STRIDE))[lane] = v;
        }
        __syncthreads();
        for (int k4 = 0; k4 < 16; k4++) {
            float4 xa = *(const float4*)(Xs + g0*XS_STRIDE + k4*4);
            float4 xb = *(const float4*)(Xs + g1*XS_STRIDE + k4*4);
            #pragma unroll
            for (int kk = 0; kk < 4; kk++) {
                const float4* wr = (const float4*)(Ws + (k4*4 + kk)*WS_STRIDE + woff);
                float fa = (&xa.x)[kk], fb = (&xb.x)[kk];
                #pragma unroll
                for (int j = 0; j < 8; j++) {
                    float4 wv = wr[j];
                    a0[j].x += fa*wv.x; a0[j].y += fa*wv.y; a0[j].z += fa*wv.z; a0[j].w += fa*wv.w;
                    a1[j].x += fb*wv.x; a1[j].y += fb*wv.y; a1[j].z += fb*wv.z; a1[j].w += fb*wv.w;
                }
            }
        }
    }
    float4* o0 = (float4*)(g_xt + ((size_t)(g0*NRr + r))*OC + oh*32);
    float4* o1 = (float4*)(g_xt + ((size_t)(g1*NRr + r))*OC + oh*32);
    #pragma unroll
    for (int j = 0; j < 8; j++) { o0[j] = a0[j]; o1[j] = a1[j]; }
}

// Deterministic per-graph CSR build, counting-sort style, all 8 warps active.
// Bucket order = ascending edge id (stable), matching XLA scatter order.
__global__ void __launch_bounds__(256) k_csr(const int* __restrict__ ei,
                                             const float* __restrict__ eattr) {
    __shared__ unsigned short ldst[EPG];
    __shared__ unsigned short lpos[EPG];
    __shared__ int cw[8][NRr];
    __shared__ int tot[NRr], off[NRr];
    int g = blockIdx.x, tid = threadIdx.x;
    int lane = tid & 31, wid = tid >> 5;
    int base = g*EPG;
    int cbeg = wid*CHUNK;

    for (int i = tid; i < EPG; i += 256)
        ldst[i] = (unsigned short)(ei[ET + base + i] - g*NRr);
    for (int i = tid; i < 8*NRr; i += 256) ((int*)cw)[i] = 0;
    __syncthreads();

    for (int i = cbeg + lane; i < cbeg + CHUNK; i += 32)
        atomicAdd(&cw[wid][ldst[i]], 1);
    __syncthreads();

    for (int d = tid; d < NRr; d += 256) {
        int s = 0;
        #pragma unroll
        for (int w = 0; w < 8; w++) s += cw[w][d];
        tot[d] = s;
    }
    __syncthreads();

    if (wid == 0) {
        int carry = 0;
        for (int c = 0; c < 9; c++) {
            int idx = c*32 + lane;
            int v = (idx < NRr) ? tot[idx] : 0;
            int incl = v;
            #pragma unroll
            for (int o = 1; o < 32; o <<= 1) {
                int t = __shfl_up_sync(0xffffffffu, incl, o);
                if (lane >= o) incl += t;
            }
            if (idx < NRr) off[idx] = incl - v + carry;
            carry += __shfl_sync(0xffffffffu, incl, 31);
        }
    }
    __syncthreads();

    for (int d = tid; d < NRr; d += 256) {
        int run = off[d];
        #pragma unroll
        for (int w = 0; w < 8; w++) { int t = cw[w][d]; cw[w][d] = run; run += t; }
        g_off[g*NRr + d] = base + off[d];
    }
    if (g == NB-1 && tid == 0) g_off[NT] = ET;
    __syncthreads();

    for (int it = 0; it < (CHUNK + 31)/32; it++) {
        int idx = cbeg + it*32 + lane;
        bool valid = (idx < cbeg + CHUNK);
        int d = valid ? (int)ldst[idx] : (NRr + lane);
        unsigned mask = __match_any_sync(0xffffffffu, d);
        int rank = __popc(mask & ((1u << lane) - 1u));
        int leader = __ffs(mask) - 1;
        int prior = valid ? cw[wid][d] : 0;
        if (valid && lane == leader) cw[wid][d] = prior + __popc(mask);
        if (valid) lpos[idx] = (unsigned short)(prior + rank);
    }
    __syncthreads();

    for (int i = tid; i < EPG; i += 256) {
        int pos = base + (int)lpos[i];
        g_bsrc[pos] = ei[base + i];
        g_bea[pos]  = eattr[base + i];
    }
}

// Fused gather + self-loop + bias + ELU + LayerNorm. Warp per dst node.
// Deterministic: fixed (edge-id ascending) summation order, self-loop last.
// Staging precomputes (s*OC, q*128, fr) packed in ONE float4 smem slot per
// edge; inner loop = 1 broadcast LDS.128 + 2 addr adds + 2 LDG + 4 FMA.
__global__ void __launch_bounds__(256) k_gather(const float* __restrict__ cbias,
                                                const float* __restrict__ gam,
                                                const float* __restrict__ bet) {
    __shared__ float4 s_p[8][128];          // (soff, qoff, fr, -) per edge, 16 KB
    int w = threadIdx.x >> 5, lane = threadIdx.x & 31;
    int n = blockIdx.x*8 + w;
    int o0 = g_off[n];
    int cnt = g_off[n+1] - o0;
    if (cnt > 128) cnt = 128;               // statistically impossible (mean 32)
    for (int j = lane; j < cnt; j += 32) {
        int s = g_bsrc[o0 + j];
        float ea = g_bea[o0 + j];
        float f = ea * (float)QT;
        int q = (int)f; if (q > QT-1) q = QT-1;
        float fr = f - (float)q;
        s_p[w][j] = make_float4(__int_as_float(s*OC),
                                __int_as_float(q*(OC*2)),
                                fr, 0.f);
    }
    __syncwarp();
    const float* tabp = g_tab2 + lane*4;    // lane's 16B slice of the table row
    const float* xtp  = g_xt   + lane*2;    // lane's 8B slice of an xt row
    float2 acc = make_float2(0.f, 0.f);
    #pragma unroll 4
    for (int j = 0; j < cnt; j++) {
        float4 pv = s_p[w][j];
        int soff = __float_as_int(pv.x);
        int qoff = __float_as_int(pv.y);
        float fr = pv.z;
        float4 tv = *(const float4*)(tabp + qoff);   // (v0,d0,v1,d1)
        float2 xv = *(const float2*)(xtp + soff);
        acc.x = fmaf(xv.x, fmaf(tv.y, fr, tv.x), acc.x);
        acc.y = fmaf(xv.y, fmaf(tv.w, fr, tv.z), acc.y);
    }
    // self-loop (appended last in reference), then bias
    float2 sg = ((const float2*)g_selfg)[lane];
    float2 xn = ((const float2*)(g_xt + (size_t)n*OC))[lane];
    acc.x += xn.x * sg.x; acc.y += xn.y * sg.y;
    float2 bb = ((const float2*)cbias)[lane];
    acc.x += bb.x; acc.y += bb.y;
    // ELU
    acc.x = acc.x > 0.f ? acc.x : expm1f(acc.x);
    acc.y = acc.y > 0.f ? acc.y : expm1f(acc.y);
    // LayerNorm (warp reduce over 64 channels)
    float s1 = acc.x + acc.y;
    #pragma unroll
    for (int o = 16; o; o >>= 1) s1 += __shfl_xor_sync(0xffffffffu, s1, o);
    float mu = s1 * (1.f/64.f);
    float dx = acc.x - mu, dy = acc.y - mu;
    float s2 = dx*dx + dy*dy;
    #pragma unroll
    for (int o = 16; o; o >>= 1) s2 += __shfl_xor_sync(0xffffffffu, s2, o);
    float inv = 1.0f / sqrtf(s2*(1.f/64.f) + LN_EPS);
    float2 gm = ((const float2*)gam)[lane];
    float2 bt = ((const float2*)bet)[lane];
    float2 h;
    h.x = dx*inv*gm.x + bt.x;
    h.y = dy*inv*gm.y + bt.y;
    ((float2*)(g_out + (size_t)n*OC))[lane] = h;
}

__device__ __forceinline__ float fast_tanh(float x) {
    // 1 - 2/(e^{2x}+1): abs err ~1e-7, handles +/-inf saturation correctly
    float e = __expf(2.0f * x);
    return 1.0f - __fdividef(2.0f, e + 1.0f);
}

// attention scores, k_xt-style tiling: thread = 2 nodes x 32 outputs.
// Block covers 256 nodes (p in [0,128), second node at +128); grid NT/256.
__global__ void __launch_bounds__(256) k_score(const float* __restrict__ W1,
                                               const float* __restrict__ b1,
                                               const float* __restrict__ w2,
                                               const float* __restrict__ b2,
                                               float* __restrict__ dout) {
    __shared__ float W1s[64*WS_STRIDE];     // 18 KB, halves at col 0 / 36
    __shared__ float b1s[OC], w2s[OC];
    int tid = threadIdx.x;
    for (int i = tid; i < 64*16; i += 256) {
        int c = i >> 4, c4 = i & 15;
        float4 v = ((const float4*)W1)[c*16 + c4];
        int col = c4*4;
        int off = (col < 32) ? col : (36 + col - 32);
        *(float4*)(W1s + c*WS_STRIDE + off) = v;
    }
    if (tid < OC) { b1s[tid] = b1[tid]; w2s[tid] = w2[tid]; }
    __syncthreads();

    int p = tid >> 1, oh = tid & 1;
    int n0 = blockIdx.x*256 + p;
    int n1 = n0 + 128;
    const float4* h0 = (const float4*)(g_out + (size_t)n0*OC);
    const float4* h1 = (const float4*)(g_out + (size_t)n1*OC);
    int woff = oh ? 36 : 0;

    float4 u0[8], u1[8];
    #pragma unroll
    for (int j = 0; j < 8; j++) {
        u0[j] = ((const float4*)(b1s + oh*32))[j];
        u1[j] = u0[j];
    }
    for (int i = 0; i < 16; i++) {
        float4 ha = h0[i], hb = h1[i];
        #pragma unroll
        for (int kk = 0; kk < 4; kk++) {
            const float4* wr = (const float4*)(W1s + (i*4 + kk)*WS_STRIDE + woff);
            float fa = (&ha.x)[kk], fb = (&hb.x)[kk];
            #pragma unroll
            for (int j = 0; j < 8; j++) {
                float4 wv = wr[j];
                u0[j].x += fa*wv.x; u0[j].y += fa*wv.y; u0[j].z += fa*wv.z; u0[j].w += fa*wv.w;
                u1[j].x += fb*wv.x; u1[j].y += fb*wv.y; u1[j].z += fb*wv.z; u1[j].w += fb*wv.w;
            }
        }
    }
    const float* w2h = w2s + oh*32;
    float p0 = 0.f, p1 = 0.f;
    #pragma unroll
    for (int j = 0; j < 8; j++) {
        p0 += fast_tanh(u0[j].x)*w2h[j*4+0] + fast_tanh(u0[j].y)*w2h[j*4+1]
            + fast_tanh(u0[j].z)*w2h[j*4+2] + fast_tanh(u0[j].w)*w2h[j*4+3];
        p1 += fast_tanh(u1[j].x)*w2h[j*4+0] + fast_tanh(u1[j].y)*w2h[j*4+1]
            + fast_tanh(u1[j].z)*w2h[j*4+2] + fast_tanh(u1[j].w)*w2h[j*4+3];
    }
    p0 += __shfl_xor_sync(0xffffffffu, p0, 1);
    p1 += __shfl_xor_sync(0xffffffffu, p1, 1);
    if (oh == 0) {
        float bv = b2[0];
        dout[SC_OFF + n0] = p0 + bv;
        dout[SC_OFF + n1] = p1 + bv;
    }
}

// per-graph top-K via full bitonic sort (desc value, tie: asc index like jax top_k)
__global__ void __launch_bounds__(512) k_top(float* __restrict__ dout) {
    __shared__ float sv[512];
    __shared__ int   si[512];
    __shared__ float ssig[KK];
    int g = blockIdx.x, t = threadIdx.x;
    sv[t] = (t < NRr) ? dout[SC_OFF + g*NRr + t] : -3.402823466e+38f;
    si[t] = t;
    __syncthreads();
    for (int k = 2; k <= 512; k <<= 1) {
        for (int j = k >> 1; j > 0; j >>= 1) {
            int ixj = t ^ j;
            if (ixj > t) {
                float av = sv[t], bv = sv[ixj];
                int ai = si[t], bi = si[ixj];
                bool aFirst = (av > bv) || (av == bv && ai < bi);
                bool up = ((t & k) == 0);
                bool doswap = up ? (!aFirst) : aFirst;
                if (doswap) { sv[t] = bv; sv[ixj] = av; si[t] = bi; si[ixj] = ai; }
            }
            __syncthreads();
        }
    }
    for (int i = t; i < KK; i += 512) {
        float v = sv[i];
        ssig[i] = 1.f / (1.f + expf(-v));
        int li = si[i];
        dout[PERM_OFF + g*KK + i] = (float)(g*NRr + li);
        dout[BAT_OFF  + g*KK + i] = (float)g;
    }
    __syncthreads();
    for (int j = t; j < KK*OC; j += 512) {
        int i = j >> 6, c = j & 63;
        int li = si[i];
        dout[XP_OFF + (size_t)(g*KK + i)*OC + c] =
            g_out[((size_t)(g*NRr + li))*OC + c] * ssig[i];
    }
}

// ---------------- launch ---------------------------------------------------
extern "C" void kernel_launch(void* const* d_in, const int* in_sizes, int n_in,
                              void* d_out, int out_size) {
    const float* x      = (const float*)d_in[0];
    const int*   ei     = (const int*)  d_in[1];
    const float* eattr  = (const float*)d_in[2];
    // d_in[3] = batch (recomputed analytically)
    const float* basis  = (const float*)d_in[4];
    const float* roicom = (const float*)d_in[5];
    const float* ew_w   = (const float*)d_in[6];
    const float* ew_b   = (const float*)d_in[7];
    const float* cbias  = (const float*)d_in[8];
    const float* gam    = (const float*)d_in[9];
    const float* bet    = (const float*)d_in[10];
    const float* W1     = (const float*)d_in[11];
    const float* b1     = (const float*)d_in[12];
    const float* w2     = (const float*)d_in[13];
    const float* b2     = (const float*)d_in[14];
    float* dout = (float*)d_out;

    static cudaStream_t s1 = (cudaStream_t)0;
    static cudaEvent_t  e0 = (cudaEvent_t)0, e1 = (cudaEvent_t)0;
    if (!s1) {
        cudaStreamCreateWithFlags(&s1, cudaStreamNonBlocking);
        cudaEventCreateWithFlags(&e0, cudaEventDisableTiming);
        cudaEventCreateWithFlags(&e1, cudaEventDisableTiming);
        cudaFuncSetAttribute(k_xt, cudaFuncAttributeMaxDynamicSharedMemorySize,
                             (XS_FLOATS + WS_FLOATS)*(int)sizeof(float));
    }

    // fork: side stream builds CSR + gate table while main stream does the GEMM
    cudaEventRecord(e0, 0);
    cudaStreamWaitEvent(s1, e0, 0);
    k_tab<<<QT+1, OC, 0, s1>>>(ew_w, ew_b);
    k_csr<<<NB, 256, 0, s1>>>(ei, eattr);
    cudaEventRecord(e1, s1);

    // main stream: fused mix+GEMM
    k_xt<<<NRr, 256, (XS_FLOATS + WS_FLOATS)*sizeof(float)>>>(x, basis, roicom);

    // join, then gather+LN -> score -> top
    cudaStreamWaitEvent(0, e1, 0);
    k_gather<<<NT/8, 256>>>(cbias, gam, bet);
    k_score<<<NT/256, 256>>>(W1, b1, w2, b2, dout);
    k_top<<<NB, 512>>>(dout);
}

// round 15
// speedup vs baseline: 1.2114x; 1.2114x over previous
#include <cuda_runtime.h>
#include <math.h>

#define NB   256            // graphs
#define NRr  268            // ROIs per graph
#define NT   (NB*NRr)       // total nodes = 68608
#define IC   256
#define OC   64
#define NCm  7
#define DEG  32
#define EPG  (NRr*DEG)      // edges per graph = 8576
#define ET   (NT*DEG)       // total edges = 2195456
#define KK   214            // top-k per graph
#define QT   256            // sigmoid table resolution
#define LN_EPS 1e-5f
#define CHUNK (EPG/8)       // 1072 edges per warp in k_csr

// k_xt smem layout
#define XS_STRIDE 68        // 256 rows (graphs) x 64 k, padded
#define WS_STRIDE 72        // 64 rows (k) x 64 out, halves at col 0 and 36
#define XS_FLOATS (256*XS_STRIDE)
#define WS_FLOATS (64*WS_STRIDE)

// output layout (float32, concatenated in reference return order)
#define XP_OFF   0
#define BAT_OFF  (NB*KK*OC)                 // 3506176
#define SC_OFF   (BAT_OFF + NB*KK)          // 3560960
#define PERM_OFF (SC_OFF + NT)              // 3629568

// ---------------- scratch (device globals; no allocation allowed) ----------
__device__ float g_tab2[QT*OC*2];           // per q,c: (sigmoid, delta) pairs, 128 KB
__device__ float g_selfg[OC];               // exact gate at ea=1 (self loops)
__device__ float g_xt[NT*OC];               // xt (per-node transform result)
__device__ float g_out[NT*OC];              // h after fused conv+ELU+LN
__device__ int   g_bsrc[ET];                // CSR bucket: global src node per slot
__device__ float g_bea[ET];                 // CSR bucket: edge_attr per slot
__device__ int   g_off[NT+1];               // CSR offsets (global edge space)

// ---------------- kernels --------------------------------------------------

// Fused ROI-kernel mix + grouped GEMM, smem-staged.
// Block = ROI r. Thread = 2 graphs x 32 outputs.
__global__ void __launch_bounds__(256, 2) k_xt(const float* __restrict__ x,
                                               const float* __restrict__ basis,
                                               const float* __restrict__ rc) {
    extern __shared__ float sm[];           // [XS_FLOATS] X | [WS_FLOATS] W
    float* Xs = sm;
    float* Ws = sm + XS_FLOATS;
    __shared__ float cws[NCm];
    int r = blockIdx.x;
    int tid = threadIdx.x;
    int w = tid >> 5, lane = tid & 31;
    int gp = tid >> 1;                      // 0..127
    int oh = tid & 1;                       // output half
    int g0 = gp, g1 = gp + 128;
    int woff = oh ? 36 : 0;

    if (tid == 0) {
        double v[NCm]; double m = -1e300;
        #pragma unroll
        for (int c = 0; c < NCm; c++) { v[c] = (double)rc[r*NCm + c]; if (v[c] > m) m = v[c]; }
        double s = 0.0;
        #pragma unroll
        for (int c = 0; c < NCm; c++) { v[c] = exp(v[c] - m); s += v[c]; }
        #pragma unroll
        for (int c = 0; c < NCm; c++) cws[c] = (float)(v[c] / s);
    }
    __syncthreads();
    float cwv[NCm];
    #pragma unroll
    for (int c = 0; c < NCm; c++) cwv[c] = cws[c];

    float4 a0[8], a1[8];
    #pragma unroll
    for (int j = 0; j < 8; j++) {
        a0[j] = make_float4(0.f,0.f,0.f,0.f);
        a1[j] = make_float4(0.f,0.f,0.f,0.f);
    }
    const float4* b4 = (const float4*)basis;

    for (int kt = 0; kt < 4; kt++) {
        __syncthreads();
        for (int i = tid; i < 64*16; i += 256) {
            int kk = i >> 4, c4 = i & 15;
            float4 acc = make_float4(0.f,0.f,0.f,0.f);
            #pragma unroll
            for (int c = 0; c < NCm; c++) {
                float4 t = b4[c*(IC*OC/4) + (kt*64 + kk)*(OC/4) + c4];
                acc.x += cwv[c]*t.x; acc.y += cwv[c]*t.y;
                acc.z += cwv[c]*t.z; acc.w += cwv[c]*t.w;
            }
            int col = c4*4;
            int off = (col < 32) ? col : (36 + col - 32);
            *(float4*)(Ws + kk*WS_STRIDE + off) = acc;
        }
        for (int g = w; g < 256; g += 8) {
            float2 v = ((const float2*)(x + ((size_t)(g*NRr + r))*IC + kt*64))[lane];
            ((float2*)(Xs + g*XS_STRIDE))[lane] = v;
        }
        __syncthreads();
        for (int k4 = 0; k4 < 16; k4++) {
            float4 xa = *(const float4*)(Xs + g0*XS_STRIDE + k4*4);
            float4 xb = *(const float4*)(Xs + g1*XS_STRIDE + k4*4);
            #pragma unroll
            for (int kk = 0; kk < 4; kk++) {
                const float4* wr = (const float4*)(Ws + (k4*4 + kk)*WS_STRIDE + woff);
                float fa = (&xa.x)[kk], fb = (&xb.x)[kk];
                #pragma unroll
                for (int j = 0; j < 8; j++) {
                    float4 wv = wr[j];
                    a0[j].x += fa*wv.x; a0[j].y += fa*wv.y; a0[j].z += fa*wv.z; a0[j].w += fa*wv.w;
                    a1[j].x += fb*wv.x; a1[j].y += fb*wv.y; a1[j].z += fb*wv.z; a1[j].w += fb*wv.w;
                }
            }
        }
    }
    float4* o0 = (float4*)(g_xt + ((size_t)(g0*NRr + r))*OC + oh*32);
    float4* o1 = (float4*)(g_xt + ((size_t)(g1*NRr + r))*OC + oh*32);
    #pragma unroll
    for (int j = 0; j < 8; j++) { o0[j] = a0[j]; o1[j] = a1[j]; }
}

// Deterministic per-graph CSR build (blocks < NB) + sigmoid table build
// (blocks >= NB: 4 table rows each). Bucket order = ascending edge id.
__global__ void __launch_bounds__(256) k_csr(const int* __restrict__ ei,
                                             const float* __restrict__ eattr,
                                             const float* __restrict__ ew_w,
                                             const float* __restrict__ ew_b) {
    __shared__ unsigned short ldst[EPG];
    __shared__ unsigned short lpos[EPG];
    __shared__ int cw[8][NRr];
    __shared__ int tot[NRr], off[NRr];
    int g = blockIdx.x, tid = threadIdx.x;

    if (g >= NB) {                          // table-builder blocks
        int q = (g - NB)*4 + (tid >> 6);
        int c = tid & 63;
        if (q > QT) return;
        double wa = (double)ew_w[c], ba = (double)ew_b[c];
        if (q == QT) {
            g_selfg[c] = (float)(1.0 / (1.0 + exp(-(wa + ba))));
            return;
        }
        double v0 = 1.0 / (1.0 + exp(-(((double)q    /(double)QT)*wa + ba)));
        double v1 = 1.0 / (1.0 + exp(-(((double)(q+1)/(double)QT)*wa + ba)));
        g_tab2[q*(OC*2) + c*2]     = (float)v0;
        g_tab2[q*(OC*2) + c*2 + 1] = (float)(v1 - v0);
        return;
    }

    int lane = tid & 31, wid = tid >> 5;
    int base = g*EPG;
    int cbeg = wid*CHUNK;

    for (int i = tid; i < EPG; i += 256)
        ldst[i] = (unsigned short)(ei[ET + base + i] - g*NRr);
    for (int i = tid; i < 8*NRr; i += 256) ((int*)cw)[i] = 0;
    __syncthreads();

    for (int i = cbeg + lane; i < cbeg + CHUNK; i += 32)
        atomicAdd(&cw[wid][ldst[i]], 1);
    __syncthreads();

    for (int d = tid; d < NRr; d += 256) {
        int s = 0;
        #pragma unroll
        for (int w = 0; w < 8; w++) s += cw[w][d];
        tot[d] = s;
    }
    __syncthreads();

    if (wid == 0) {
        int carry = 0;
        for (int c = 0; c < 9; c++) {
            int idx = c*32 + lane;
            int v = (idx < NRr) ? tot[idx] : 0;
            int incl = v;
            #pragma unroll
            for (int o = 1; o < 32; o <<= 1) {
                int t = __shfl_up_sync(0xffffffffu, incl, o);
                if (lane >= o) incl += t;
            }
            if (idx < NRr) off[idx] = incl - v + carry;
            carry += __shfl_sync(0xffffffffu, incl, 31);
        }
    }
    __syncthreads();

    for (int d = tid; d < NRr; d += 256) {
        int run = off[d];
        #pragma unroll
        for (int w = 0; w < 8; w++) { int t = cw[w][d]; cw[w][d] = run; run += t; }
        g_off[g*NRr + d] = base + off[d];
    }
    if (g == NB-1 && tid == 0) g_off[NT] = ET;
    __syncthreads();

    for (int it = 0; it < (CHUNK + 31)/32; it++) {
        int idx = cbeg + it*32 + lane;
        bool valid = (idx < cbeg + CHUNK);
        int d = valid ? (int)ldst[idx] : (NRr + lane);
        unsigned mask = __match_any_sync(0xffffffffu, d);
        int rank = __popc(mask & ((1u << lane) - 1u));
        int leader = __ffs(mask) - 1;
        int prior = valid ? cw[wid][d] : 0;
        if (valid && lane == leader) cw[wid][d] = prior + __popc(mask);
        if (valid) lpos[idx] = (unsigned short)(prior + rank);
    }
    __syncthreads();

    for (int i = tid; i < EPG; i += 256) {
        int pos = base + (int)lpos[i];
        g_bsrc[pos] = ei[base + i];
        g_bea[pos]  = eattr[base + i];
    }
}

// Fused gather + self-loop + bias + ELU + LayerNorm. Warp per dst node.
// Deterministic: fixed (edge-id ascending) summation order, self-loop last.
// Inner loop: merged (v,delta) float4 table load + xt float2 + inline q/fr.
__global__ void __launch_bounds__(256) k_gather(const float* __restrict__ cbias,
                                                const float* __restrict__ gam,
                                                const float* __restrict__ bet) {
    __shared__ int   s_s[8][128];
    __shared__ float s_e[8][128];
    int w = threadIdx.x >> 5, lane = threadIdx.x & 31;
    int n = blockIdx.x*8 + w;
    int o0 = g_off[n];
    int cnt = g_off[n+1] - o0;
    if (cnt > 128) cnt = 128;               // statistically impossible (mean 32)
    for (int j = lane; j < cnt; j += 32) {
        s_s[w][j] = g_bsrc[o0 + j];
        s_e[w][j] = g_bea [o0 + j];
    }
    __syncwarp();
    float2 acc = make_float2(0.f, 0.f);
    #pragma unroll 4
    for (int j = 0; j < cnt; j++) {
        int s = s_s[w][j];
        float ea = s_e[w][j];
        float f = ea * (float)QT;
        int q = (int)f; if (q > QT-1) q = QT-1;
        float fr = f - (float)q;
        float4 tv = *(const float4*)(g_tab2 + q*(OC*2) + lane*4);  // (v0,d0,v1,d1)
        float2 xv = ((const float2*)(g_xt + (size_t)s*OC))[lane];
        acc.x = fmaf(xv.x, fmaf(tv.y, fr, tv.x), acc.x);
        acc.y = fmaf(xv.y, fmaf(tv.w, fr, tv.z), acc.y);
    }
    // self-loop (appended last in reference), then bias
    float2 sg = ((const float2*)g_selfg)[lane];
    float2 xn = ((const float2*)(g_xt + (size_t)n*OC))[lane];
    acc.x += xn.x * sg.x; acc.y += xn.y * sg.y;
    float2 bb = ((const float2*)cbias)[lane];
    acc.x += bb.x; acc.y += bb.y;
    // ELU
    acc.x = acc.x > 0.f ? acc.x : expm1f(acc.x);
    acc.y = acc.y > 0.f ? acc.y : expm1f(acc.y);
    // LayerNorm (warp reduce over 64 channels)
    float s1 = acc.x + acc.y;
    #pragma unroll
    for (int o = 16; o; o >>= 1) s1 += __shfl_xor_sync(0xffffffffu, s1, o);
    float mu = s1 * (1.f/64.f);
    float dx = acc.x - mu, dy = acc.y - mu;
    float s2 = dx*dx + dy*dy;
    #pragma unroll
    for (int o = 16; o; o >>= 1) s2 += __shfl_xor_sync(0xffffffffu, s2, o);
    float inv = 1.0f / sqrtf(s2*(1.f/64.f) + LN_EPS);
    float2 gm = ((const float2*)gam)[lane];
    float2 bt = ((const float2*)bet)[lane];
    float2 h;
    h.x = dx*inv*gm.x + bt.x;
    h.y = dy*inv*gm.y + bt.y;
    ((float2*)(g_out + (size_t)n*OC))[lane] = h;
}

__device__ __forceinline__ float fast_tanh(float x) {
    // 1 - 2/(e^{2x}+1): abs err ~1e-7, handles +/-inf saturation correctly
    float e = __expf(2.0f * x);
    return 1.0f - __fdividef(2.0f, e + 1.0f);
}

// attention scores, k_xt-style tiling: thread = 2 nodes x 32 outputs.
// Block covers 256 nodes (p in [0,128), second node at +128); grid NT/256.
__global__ void __launch_bounds__(256) k_score(const float* __restrict__ W1,
                                               const float* __restrict__ b1,
                                               const float* __restrict__ w2,
                                               const float* __restrict__ b2,
                                               float* __restrict__ dout) {
    __shared__ float W1s[64*WS_STRIDE];     // 18 KB, halves at col 0 / 36
    __shared__ float b1s[OC], w2s[OC];
    int tid = threadIdx.x;
    for (int i = tid; i < 64*16; i += 256) {
        int c = i >> 4, c4 = i & 15;
        float4 v = ((const float4*)W1)[c*16 + c4];
        int col = c4*4;
        int off = (col < 32) ? col : (36 + col - 32);
        *(float4*)(W1s + c*WS_STRIDE + off) = v;
    }
    if (tid < OC) { b1s[tid] = b1[tid]; w2s[tid] = w2[tid]; }
    __syncthreads();

    int p = tid >> 1, oh = tid & 1;
    int n0 = blockIdx.x*256 + p;
    int n1 = n0 + 128;
    const float4* h0 = (const float4*)(g_out + (size_t)n0*OC);
    const float4* h1 = (const float4*)(g_out + (size_t)n1*OC);
    int woff = oh ? 36 : 0;

    float4 u0[8], u1[8];
    #pragma unroll
    for (int j = 0; j < 8; j++) {
        u0[j] = ((const float4*)(b1s + oh*32))[j];
        u1[j] = u0[j];
    }
    for (int i = 0; i < 16; i++) {
        float4 ha = h0[i], hb = h1[i];
        #pragma unroll
        for (int kk = 0; kk < 4; kk++) {
            const float4* wr = (const float4*)(W1s + (i*4 + kk)*WS_STRIDE + woff);
            float fa = (&ha.x)[kk], fb = (&hb.x)[kk];
            #pragma unroll
            for (int j = 0; j < 8; j++) {
                float4 wv = wr[j];
                u0[j].x += fa*wv.x; u0[j].y += fa*wv.y; u0[j].z += fa*wv.z; u0[j].w += fa*wv.w;
                u1[j].x += fb*wv.x; u1[j].y += fb*wv.y; u1[j].z += fb*wv.z; u1[j].w += fb*wv.w;
            }
        }
    }
    const float* w2h = w2s + oh*32;
    float p0 = 0.f, p1 = 0.f;
    #pragma unroll
    for (int j = 0; j < 8; j++) {
        p0 += fast_tanh(u0[j].x)*w2h[j*4+0] + fast_tanh(u0[j].y)*w2h[j*4+1]
            + fast_tanh(u0[j].z)*w2h[j*4+2] + fast_tanh(u0[j].w)*w2h[j*4+3];
        p1 += fast_tanh(u1[j].x)*w2h[j*4+0] + fast_tanh(u1[j].y)*w2h[j*4+1]
            + fast_tanh(u1[j].z)*w2h[j*4+2] + fast_tanh(u1[j].w)*w2h[j*4+3];
    }
    p0 += __shfl_xor_sync(0xffffffffu, p0, 1);
    p1 += __shfl_xor_sync(0xffffffffu, p1, 1);
    if (oh == 0) {
        float bv = b2[0];
        dout[SC_OFF + n0] = p0 + bv;
        dout[SC_OFF + n1] = p1 + bv;
    }
}

// per-graph top-K via full bitonic sort (desc value, tie: asc index like jax top_k)
__global__ void __launch_bounds__(512) k_top(float* __restrict__ dout) {
    __shared__ float sv[512];
    __shared__ int   si[512];
    __shared__ float ssig[KK];
    int g = blockIdx.x, t = threadIdx.x;
    sv[t] = (t < NRr) ? dout[SC_OFF + g*NRr + t] : -3.402823466e+38f;
    si[t] = t;
    __syncthreads();
    for (int k = 2; k <= 512; k <<= 1) {
        for (int j = k >> 1; j > 0; j >>= 1) {
            int ixj = t ^ j;
            if (ixj > t) {
                float av = sv[t], bv = sv[ixj];
                int ai = si[t], bi = si[ixj];
                bool aFirst = (av > bv) || (av == bv && ai < bi);
                bool up = ((t & k) == 0);
                bool doswap = up ? (!aFirst) : aFirst;
                if (doswap) { sv[t] = bv; sv[ixj] = av; si[t] = bi; si[ixj] = ai; }
            }
            __syncthreads();
        }
    }
    for (int i = t; i < KK; i += 512) {
        float v = sv[i];
        ssig[i] = 1.f / (1.f + expf(-v));
        int li = si[i];
        dout[PERM_OFF + g*KK + i] = (float)(g*NRr + li);
        dout[BAT_OFF  + g*KK + i] = (float)g;
    }
    __syncthreads();
    for (int j = t; j < KK*OC; j += 512) {
        int i = j >> 6, c = j & 63;
        int li = si[i];
        dout[XP_OFF + (size_t)(g*KK + i)*OC + c] =
            g_out[((size_t)(g*NRr + li))*OC + c] * ssig[i];
    }
}

// ---------------- launch ---------------------------------------------------
extern "C" void kernel_launch(void* const* d_in, const int* in_sizes, int n_in,
                              void* d_out, int out_size) {
    const float* x      = (const float*)d_in[0];
    const int*   ei     = (const int*)  d_in[1];
    const float* eattr  = (const float*)d_in[2];
    // d_in[3] = batch (recomputed analytically)
    const float* basis  = (const float*)d_in[4];
    const float* roicom = (const float*)d_in[5];
    const float* ew_w   = (const float*)d_in[6];
    const float* ew_b   = (const float*)d_in[7];
    const float* cbias  = (const float*)d_in[8];
    const float* gam    = (const float*)d_in[9];
    const float* bet    = (const float*)d_in[10];
    const float* W1     = (const float*)d_in[11];
    const float* b1     = (const float*)d_in[12];
    const float* w2     = (const float*)d_in[13];
    const float* b2     = (const float*)d_in[14];
    float* dout = (float*)d_out;

    static cudaStream_t s1 = (cudaStream_t)0;
    static cudaEvent_t  e0 = (cudaEvent_t)0, e1 = (cudaEvent_t)0;
    if (!s1) {
        cudaStreamCreateWithFlags(&s1, cudaStreamNonBlocking);
        cudaEventCreateWithFlags(&e0, cudaEventDisableTiming);
        cudaEventCreateWithFlags(&e1, cudaEventDisableTiming);
        cudaFuncSetAttribute(k_xt, cudaFuncAttributeMaxDynamicSharedMemorySize,
                             (XS_FLOATS + WS_FLOATS)*(int)sizeof(float));
    }

    // fork: side stream builds CSR + gate table while main stream does the GEMM
    cudaEventRecord(e0, 0);
    cudaStreamWaitEvent(s1, e0, 0);
    k_csr<<<NB + 65, 256, 0, s1>>>(ei, eattr, ew_w, ew_b);
    cudaEventRecord(e1, s1);

    // main stream: fused mix+GEMM
    k_xt<<<NRr, 256, (XS_FLOATS + WS_FLOATS)*sizeof(float)>>>(x, basis, roicom);

    // join, then gather+LN -> score -> top
    cudaStreamWaitEvent(0, e1, 0);
    k_gather<<<NT/8, 256>>>(cbias, gam, bet);
    k_score<<<NT/256, 256>>>(W1, b1, w2, b2, dout);
    k_top<<<NB, 512>>>(dout);
}